// round 16
// baseline (speedup 1.0000x reference)
#include <cuda_runtime.h>

#define NCLS 19
#define FPX  16384      // 128*128 feature pixels
#define DCH  64
#define LBL  512
#define NT   256
#define NBLK (NCLS * (DCH / 2))   // 608 klass blocks

__device__ unsigned char g_cnt8[NCLS * FPX];   // per-class per-pixel weights (0..16)
__device__ float g_loss[NBLK];
__device__ float g_n[NCLS];
__device__ unsigned g_tick;

__device__ __forceinline__ float ex2f(float x) {
    float y; asm("ex2.approx.ftz.f32 %0, %1;" : "=f"(y) : "f"(x)); return y;
}

// recurrence constants (exponent -12.5(k-t)^2 in base 2, scaled by 2^100):
#define CLK  (-18.033688011112042f)    // -12.5*log2(e)
#define RA   (-36.06737602222409f)     // -25*log2(e)
#define RB   (90.16844005556021f)      //  62.5*log2(e)
#define CC1  (1.3887943864964021e-11f) // exp(-25)
#define CC2  (1.9287498479639178e-22f) // exp(-50)

// K1: per-(pixel,class) 4x4 counts. grid (FPX/64, NCLS): high warp count,
// label re-reads are L2 hits.
__global__ __launch_bounds__(64) void count_kernel(const int* __restrict__ label) {
    const int fp  = blockIdx.x * 64 + threadIdx.x;
    const int cls = blockIdx.y;
    const int r = fp >> 7, c = fp & 127;
    const int4* lp = reinterpret_cast<const int4*>(label + (r * 4) * LBL + c * 4);
    const unsigned u = (unsigned)cls * 0x01010101u;
    int s = 0;
#pragma unroll
    for (int dr = 0; dr < 4; dr++) {
        int4 v = lp[dr * (LBL / 4)];
        unsigned pk = (unsigned)v.x | ((unsigned)v.y << 8) |
                      ((unsigned)v.z << 16) | ((unsigned)v.w << 24);
        s = __dp4a((int)(__vcmpeq4(pk, u) & 0x01010101u), 0x01010101, s);
    }
    g_cnt8[cls * FPX + fp] = (unsigned char)s;
}

// scalar 4-bank recurrence for one pixel in one channel
__device__ __forceinline__ void px_work(float f, float w, float invs, float nmu,
                                        float* accP, float* accN) {
    float t = fmaf(f, invs, nmu);
    float a = fabsf(t);
    float x = 3.0f - a;
    float g = ex2f(fmaf(CLK * x, x, 100.0f));
    float r = ex2f(fmaf(RA, a, RB));
    float wp = (t >= 0.0f) ? w : 0.0f;
    float wn = w - wp;
    accP[0] = fmaf(wp, g, accP[0]); accN[0] = fmaf(wn, g, accN[0]);
    g *= r;
    accP[1] = fmaf(wp, g, accP[1]); accN[1] = fmaf(wn, g, accN[1]);
    g *= r * CC1;
    accP[2] = fmaf(wp, g, accP[2]); accN[2] = fmaf(wn, g, accN[2]);
    g *= r * CC2;
    accP[3] = fmaf(wp, g, accP[3]); accN[3] = fmaf(wn, g, accN[3]);
}

// per-channel loss from 8 reduced bank sums
__device__ __forceinline__ float chan_loss(const float* P, const float* N) {
    // P bank s -> bin 6-s ; N bank s -> bin s (far banks truncated: <=4e-6 rel)
    float sbin[7];
    sbin[0] = N[0]; sbin[1] = N[1]; sbin[2] = N[2];
    sbin[3] = P[3] + N[3];
    sbin[4] = P[2]; sbin[5] = P[1]; sbin[6] = P[0];
    float tot = 0.f;
#pragma unroll
    for (int ib = 0; ib < 7; ib++) tot += sbin[ib];
    float inv = 1.0f / fmaxf(tot, 1e-30f);
    const float targ[7] = {0.00443305f, 0.05400558f, 0.24203623f, 0.39905027f,
                           0.24203623f, 0.05400558f, 0.00443305f};
    float L = 0.f;
#pragma unroll
    for (int ib = 0; ib < 7; ib++) {
        float dif = fabsf(sbin[ib] * inv - targ[ib]);
        L += (dif < 1.0f) ? 0.5f * dif * dif : (dif - 0.5f);
    }
    return L;
}

// K2: dense streaming, one block per (cls, channel-pair).
__global__ __launch_bounds__(NT) void klass_kernel(const float* __restrict__ feat,
                                                   float* __restrict__ outp) {
    const int cls = blockIdx.x, dp = blockIdx.y;          // dp: channel pair
    const float4* __restrict__ fa4 = reinterpret_cast<const float4*>(feat + (2 * dp) * FPX);
    const float4* __restrict__ fb4 = reinterpret_cast<const float4*>(feat + (2 * dp + 1) * FPX);
    const uchar4* __restrict__ cb  = reinterpret_cast<const uchar4*>(g_cnt8 + cls * FPX);
    const int tid = threadIdx.x, lane = tid & 31, wid = tid >> 5;

    __shared__ float red[21][8];
    __shared__ bool amlast;

    // ---- pass 1: moments for both channels (s0 shared) ----
    float s0 = 0.f, s1a = 0.f, s2a = 0.f, s1b = 0.f, s2b = 0.f;
    for (int i = tid; i < FPX / 4; i += NT) {
        float4 va = fa4[i];
        float4 vb = fb4[i];
        uchar4 wv = cb[i];
        float w0 = (float)wv.x, w1 = (float)wv.y, w2 = (float)wv.z, w3 = (float)wv.w;
        s0 += (w0 + w1) + (w2 + w3);
        float wfa0 = w0 * va.x, wfa1 = w1 * va.y, wfa2 = w2 * va.z, wfa3 = w3 * va.w;
        s1a += (wfa0 + wfa1) + (wfa2 + wfa3);
        s2a = fmaf(wfa0, va.x, fmaf(wfa1, va.y, fmaf(wfa2, va.z, fmaf(wfa3, va.w, s2a))));
        float wfb0 = w0 * vb.x, wfb1 = w1 * vb.y, wfb2 = w2 * vb.z, wfb3 = w3 * vb.w;
        s1b += (wfb0 + wfb1) + (wfb2 + wfb3);
        s2b = fmaf(wfb0, vb.x, fmaf(wfb1, vb.y, fmaf(wfb2, vb.z, fmaf(wfb3, vb.w, s2b))));
    }
    {
        float v0 = s0, v1 = s1a, v2 = s2a, v3 = s1b, v4 = s2b;
#pragma unroll
        for (int o = 16; o; o >>= 1) {
            v0 += __shfl_xor_sync(0xffffffffu, v0, o);
            v1 += __shfl_xor_sync(0xffffffffu, v1, o);
            v2 += __shfl_xor_sync(0xffffffffu, v2, o);
            v3 += __shfl_xor_sync(0xffffffffu, v3, o);
            v4 += __shfl_xor_sync(0xffffffffu, v4, o);
        }
        if (lane == 0) {
            red[0][wid] = v0; red[1][wid] = v1; red[2][wid] = v2;
            red[3][wid] = v3; red[4][wid] = v4;
        }
    }
    __syncthreads();
    float n = 0.f, S1a = 0.f, S2a = 0.f, S1b = 0.f, S2b = 0.f;
#pragma unroll
    for (int j = 0; j < 8; j++) {
        n += red[0][j]; S1a += red[1][j]; S2a += red[2][j];
        S1b += red[3][j]; S2b += red[4][j];
    }

    float loss = 0.f;
    const bool active = (n >= 1000.0f);
    if (active) {
        float nsafe = fmaxf(n, 1.0f);
        float miua = S1a / nsafe;
        float vara = fmaxf(S2a / nsafe - miua * miua, 0.0f) + 1e-10f;
        float invsa = rsqrtf(vara);
        float nmua  = -miua * invsa;
        float miub = S1b / nsafe;
        float varb = fmaxf(S2b / nsafe - miub * miub, 0.0f) + 1e-10f;
        float invsb = rsqrtf(varb);
        float nmub  = -miub * invsb;

        // ---- pass 2: 4-bank recurrence KDE, both channels ----
        float accPa[4] = {0.f, 0.f, 0.f, 0.f}, accNa[4] = {0.f, 0.f, 0.f, 0.f};
        float accPb[4] = {0.f, 0.f, 0.f, 0.f}, accNb[4] = {0.f, 0.f, 0.f, 0.f};

        for (int i = tid; i < FPX / 4; i += NT) {
            float4 va = fa4[i];
            float4 vb = fb4[i];
            uchar4 wv = cb[i];
            float w0 = (float)wv.x, w1 = (float)wv.y, w2 = (float)wv.z, w3 = (float)wv.w;
            px_work(va.x, w0, invsa, nmua, accPa, accNa);
            px_work(va.y, w1, invsa, nmua, accPa, accNa);
            px_work(va.z, w2, invsa, nmua, accPa, accNa);
            px_work(va.w, w3, invsa, nmua, accPa, accNa);
            px_work(vb.x, w0, invsb, nmub, accPb, accNb);
            px_work(vb.y, w1, invsb, nmub, accPb, accNb);
            px_work(vb.z, w2, invsb, nmub, accPb, accNb);
            px_work(vb.w, w3, invsb, nmub, accPb, accNb);
        }

        // block-reduce 16 bank sums
        float bank[16];
#pragma unroll
        for (int k = 0; k < 4; k++) {
            bank[k]      = accPa[k];
            bank[4 + k]  = accNa[k];
            bank[8 + k]  = accPb[k];
            bank[12 + k] = accNb[k];
        }
#pragma unroll
        for (int k = 0; k < 16; k++) {
            float v = bank[k];
#pragma unroll
            for (int o = 16; o; o >>= 1) v += __shfl_xor_sync(0xffffffffu, v, o);
            if (lane == 0) red[5 + k][wid] = v;
        }
        __syncthreads();

        if (tid == 0) {
            float Pa[4], Na[4], Pb[4], Nb[4];
#pragma unroll
            for (int k = 0; k < 4; k++) {
                float a0 = 0.f, a1 = 0.f, a2 = 0.f, a3 = 0.f;
#pragma unroll
                for (int w = 0; w < 8; w++) {
                    a0 += red[5 + k][w];  a1 += red[9 + k][w];
                    a2 += red[13 + k][w]; a3 += red[17 + k][w];
                }
                Pa[k] = a0; Na[k] = a1; Pb[k] = a2; Nb[k] = a3;
            }
            loss = (chan_loss(Pa, Na) + chan_loss(Pb, Nb)) * (1.0f / (7.0f * (float)DCH));
        }
    }

    if (tid == 0) {
        g_loss[cls * (DCH / 2) + dp] = loss;
        if (dp == 0) g_n[cls] = n;
    }
    __threadfence();
    if (tid == 0) {
        unsigned t = atomicAdd(&g_tick, 1u);
        amlast = (t == (unsigned)(NBLK - 1));
    }
    __syncthreads();

    if (amlast) {
        __threadfence();
        float s = 0.f;
        for (int i = tid; i < NBLK; i += NT) s += g_loss[i];
#pragma unroll
        for (int o = 16; o; o >>= 1) s += __shfl_xor_sync(0xffffffffu, s, o);
        if (lane == 0) red[0][wid] = s;
        __syncthreads();
        if (tid == 0) {
            float num = 0.f;
#pragma unroll
            for (int j = 0; j < 8; j++) num += red[0][j];
            float den = 0.f;
#pragma unroll
            for (int c = 0; c < NCLS; c++) den += (g_n[c] >= 1000.0f) ? 1.0f : 0.0f;
            outp[0] = num / den;
            g_tick = 0u;   // reset for next graph replay
        }
    }
}

extern "C" void kernel_launch(void* const* d_in, const int* in_sizes, int n_in,
                              void* d_out, int out_size) {
    const float* feature;
    const int*   label;
    if (in_sizes[0] == DCH * FPX) {
        feature = (const float*)d_in[0];
        label   = (const int*)d_in[1];
    } else {
        feature = (const float*)d_in[1];
        label   = (const int*)d_in[0];
    }
    count_kernel<<<dim3(FPX / 64, NCLS), 64>>>(label);
    klass_kernel<<<dim3(NCLS, DCH / 2), NT>>>(feature, (float*)d_out);
}

// round 17
// speedup vs baseline: 1.0275x; 1.0275x over previous
#include <cuda_runtime.h>

#define NCLS 19
#define FPX  16384      // 128*128 feature pixels
#define DCH  64
#define LBL  512
#define SCH  64         // list chunks (grid.y of mom/kde)
#define NTP  256
#define PADQ 1024       // list pad quantum -> chunk len multiple of 16
#define CHPX 8192

__device__ unsigned char g_cnt8[NCLS * FPX];
__device__ unsigned int  g_pairs[NCLS * FPX];   // (w<<16)|pixel, zero-padded
__device__ int           g_len[NCLS];
__device__ float         g_n[NCLS];
__device__ float         g_ft[FPX * DCH];       // transposed feature [p][d]
__device__ float         g_m1p[NCLS * DCH * SCH];       // [cls][ch][s]
__device__ float         g_m2p[NCLS * DCH * SCH];       // [cls][ch][s]
__device__ float         g_binp[NCLS * DCH * SCH * 8];  // [cls][ch][sb][8]
__device__ float         g_closs[NCLS];
__device__ int           g_ctick[NCLS];
__device__ int           g_gtick;

typedef unsigned long long ull;

__device__ __forceinline__ float ex2f(float x) {
    float y; asm("ex2.approx.ftz.f32 %0, %1;" : "=f"(y) : "f"(x)); return y;
}
__device__ __forceinline__ ull pk2(float lo, float hi) {
    ull r; asm("mov.b64 %0, {%1, %2};" : "=l"(r) : "f"(lo), "f"(hi)); return r;
}
__device__ __forceinline__ void upk2(float& lo, float& hi, ull v) {
    asm("mov.b64 {%0, %1}, %2;" : "=f"(lo), "=f"(hi) : "l"(v));
}
__device__ __forceinline__ ull fma2(ull a, ull b, ull c) {
    ull d; asm("fma.rn.f32x2 %0, %1, %2, %3;" : "=l"(d) : "l"(a), "l"(b), "l"(c)); return d;
}
__device__ __forceinline__ ull mul2(ull a, ull b) {
    ull d; asm("mul.rn.f32x2 %0, %1, %2;" : "=l"(d) : "l"(a), "l"(b)); return d;
}

// recurrence constants (exponent -12.5(k-t)^2 in base 2, scaled by 2^100):
#define CLK  (-18.033688011112042f)    // -12.5*log2(e)
#define RA   (-36.06737602222409f)     // -25*log2(e)
#define RB   (90.16844005556021f)      //  62.5*log2(e)
#define CC1  (1.3887943864964021e-11f) // exp(-25)
#define CC2  (1.9287498479639178e-22f) // exp(-50)

// ───── K0: prep = feature transpose (blocks 0..255) + label counts (256..319)
__global__ __launch_bounds__(256) void prep_kernel(const float* __restrict__ feat,
                                                   const int* __restrict__ label) {
    __shared__ float sm[64][65];
    const int bi = blockIdx.x, tid = threadIdx.x;
    if (bi < 256) {
        const int pixbase = bi * 64;
        const int sub = tid >> 6, low = tid & 63;
#pragma unroll
        for (int it = 0; it < 16; it++) {
            int d = sub + it * 4;
            sm[d][low] = feat[d * FPX + pixbase + low];
        }
        __syncthreads();
#pragma unroll
        for (int it = 0; it < 16; it++) {
            int p_off = sub + it * 4;
            g_ft[(pixbase + p_off) * 64 + low] = sm[low][p_off];
        }
    } else {
        const int fp = (bi - 256) * 256 + tid;
        const int r = fp >> 7, c = fp & 127;
        const int4* lp = reinterpret_cast<const int4*>(label + (r * 4) * LBL + c * 4);
        unsigned pk[4];
#pragma unroll
        for (int dr = 0; dr < 4; dr++) {
            int4 v = lp[dr * (LBL / 4)];
            pk[dr] = (unsigned)v.x | ((unsigned)v.y << 8) |
                     ((unsigned)v.z << 16) | ((unsigned)v.w << 24);
        }
#pragma unroll
        for (int cls = 0; cls < NCLS; cls++) {
            unsigned u = (unsigned)cls * 0x01010101u;
            int s = 0;
#pragma unroll
            for (int dr = 0; dr < 4; dr++)
                s = __dp4a((int)(__vcmpeq4(pk[dr], u) & 0x01010101u), 0x01010101, s);
            g_cnt8[cls * FPX + fp] = (unsigned char)s;
        }
    }
}

// ───── K1: ordered compaction (one block per class)
__global__ __launch_bounds__(NTP) void compact_kernel() {
    const int cls = blockIdx.x;
    const int tid = threadIdx.x, lane = tid & 31, wid = tid >> 5;
    __shared__ unsigned sbuf[CHPX];
    __shared__ unsigned wtot[8], wbase[8];
    __shared__ int wsumw[8];
    __shared__ unsigned chtot_s;
    __shared__ int nacc_s;

    if (tid == 0) nacc_s = 0;
    unsigned gbase = 0;
    unsigned int* __restrict__ out = g_pairs + cls * FPX;

    for (int h = 0; h < FPX / CHPX; h++) {
        const int pxbase = h * CHPX + tid * 32;
        unsigned d[8];
        const uint4* src = reinterpret_cast<const uint4*>(g_cnt8 + cls * FPX + h * CHPX)
                           + tid * 2;
        uint4 v0 = src[0], v1 = src[1];
        d[0]=v0.x; d[1]=v0.y; d[2]=v0.z; d[3]=v0.w;
        d[4]=v1.x; d[5]=v1.y; d[6]=v1.z; d[7]=v1.w;

        int nnz = 0, ws = 0;
#pragma unroll
        for (int j = 0; j < 8; j++) {
            unsigned u = d[j];
            nnz += __popc(__vcmpne4(u, 0u) & 0x01010101u);
            ws  += __dp4a((int)u, 0x01010101, 0);
        }
        unsigned inc = (unsigned)nnz;
#pragma unroll
        for (int o = 1; o < 32; o <<= 1) {
            unsigned t = __shfl_up_sync(0xffffffffu, inc, o);
            if (lane >= o) inc += t;
        }
        if (lane == 31) wtot[wid] = inc;
        int wsr = ws;
#pragma unroll
        for (int o = 16; o; o >>= 1) wsr += __shfl_xor_sync(0xffffffffu, wsr, o);
        if (lane == 0) wsumw[wid] = wsr;
        __syncthreads();
        if (tid == 0) {
            unsigned run = 0; int ns = 0;
#pragma unroll
            for (int j = 0; j < 8; j++) { wbase[j] = run; run += wtot[j]; ns += wsumw[j]; }
            chtot_s = run;
            nacc_s += ns;
        }
        __syncthreads();

        unsigned rank = wbase[wid] + inc - (unsigned)nnz;
#pragma unroll
        for (int j = 0; j < 8; j++) {
            unsigned u = d[j];
#pragma unroll
            for (int b = 0; b < 4; b++) {
                unsigned w = (u >> (8 * b)) & 0xffu;
                if (w) sbuf[rank++] = (w << 16) | (unsigned)(pxbase + j * 4 + b);
            }
        }
        __syncthreads();
        unsigned chtot = chtot_s;
        for (unsigned j = tid; j < chtot; j += NTP) out[gbase + j] = sbuf[j];
        gbase += chtot;
        __syncthreads();
    }
    unsigned pl = (gbase + PADQ - 1) / PADQ * PADQ;
    for (unsigned k = gbase + tid; k < pl; k += NTP) out[k] = 0u;
    if (tid == 0) { g_len[cls] = (int)pl; g_n[cls] = (float)nacc_s; }
}

// ───── K2: partial moments per (class, chunk), contiguous entries.
__global__ __launch_bounds__(256) void mom_kernel() {
    const int cls = blockIdx.x, s = blockIdx.y;
    if (g_n[cls] < 1000.0f) return;
    const int tid = threadIdx.x, lane = tid & 31, wid = tid >> 5;
    const int clen = g_len[cls] >> 6;          // multiple of 16
    const unsigned* __restrict__ pe = g_pairs + cls * FPX + s * clen;
    const float2* __restrict__ ft2 = reinterpret_cast<const float2*>(g_ft);

    ull s1 = 0ull, s2 = 0ull;
    for (int i = 2 * wid; i < clen; i += 16) {
        unsigned pa = __ldg(pe + i);
        unsigned pb = __ldg(pe + i + 1);
        float2 fa = ft2[(pa & 0xFFFFu) * 32 + lane];
        float2 fc = ft2[(pb & 0xFFFFu) * 32 + lane];
        float wa = (float)(pa >> 16), wb = (float)(pb >> 16);
        ull fa2 = pk2(fa.x, fa.y), fc2 = pk2(fc.x, fc.y);
        ull wa2 = pk2(wa, wa),     wb2 = pk2(wb, wb);
        s1 = fma2(fa2, wa2, s1);
        s2 = fma2(mul2(fa2, fa2), wa2, s2);
        s1 = fma2(fc2, wb2, s1);
        s2 = fma2(mul2(fc2, fc2), wb2, s2);
    }
    __shared__ float2 sm1[8][32], sm2[8][32];
    float l1, h1, l2, h2;
    upk2(l1, h1, s1); upk2(l2, h2, s2);
    sm1[wid][lane] = make_float2(l1, h1);
    sm2[wid][lane] = make_float2(l2, h2);
    __syncthreads();
    if (tid < 32) {
        float a = 0.f, b = 0.f, c = 0.f, d = 0.f;
#pragma unroll
        for (int w = 0; w < 8; w++) {
            a += sm1[w][tid].x; b += sm1[w][tid].y;
            c += sm2[w][tid].x; d += sm2[w][tid].y;
        }
        g_m1p[(cls * DCH + 2 * tid) * SCH + s]     = a;
        g_m1p[(cls * DCH + 2 * tid + 1) * SCH + s] = b;
        g_m2p[(cls * DCH + 2 * tid) * SCH + s]     = c;
        g_m2p[(cls * DCH + 2 * tid + 1) * SCH + s] = d;
    }
}

// scalar 4-bank recurrence for one pixel in one channel
__device__ __forceinline__ void px_work(float f, float w, float invs, float nmu,
                                        float* accP, float* accN) {
    float t = fmaf(f, invs, nmu);
    float a = fabsf(t);
    float x = 3.0f - a;
    float g = ex2f(fmaf(CLK * x, x, 100.0f));
    float r = ex2f(fmaf(RA, a, RB));
    float wp = (t >= 0.0f) ? w : 0.0f;
    float wn = w - wp;
    accP[0] = fmaf(wp, g, accP[0]); accN[0] = fmaf(wn, g, accN[0]);
    g *= r;
    accP[1] = fmaf(wp, g, accP[1]); accN[1] = fmaf(wn, g, accN[1]);
    g *= r * CC1;
    accP[2] = fmaf(wp, g, accP[2]); accN[2] = fmaf(wn, g, accN[2]);
    g *= r * CC2;
    accP[3] = fmaf(wp, g, accP[3]); accN[3] = fmaf(wn, g, accN[3]);
}

// ───── K3: transposed KDE, smem-staged entry list, scalar 4-bank fold.
__global__ __launch_bounds__(128, 8) void kde_kernel(float* __restrict__ outp) {
    const int cls = blockIdx.x, sb = blockIdx.y;
    const int tid = threadIdx.x, lane = tid & 31, wid = tid >> 5;
    const float n = g_n[cls];
    const bool active = (n >= 1000.0f);

    __shared__ int   sidx[FPX / SCH];          // px*32 per entry (<=256)
    __shared__ float swt[FPX / SCH];
    __shared__ float sinv[DCH], snmu[DCH];
    __shared__ float2 stgP[4][32][4], stgN[4][32][4];
    __shared__ float red[4];
    __shared__ int sflag, gflag;

    if (active && tid < DCH) {
        const float4* m1 = reinterpret_cast<const float4*>(g_m1p + (cls * DCH + tid) * SCH);
        const float4* m2 = reinterpret_cast<const float4*>(g_m2p + (cls * DCH + tid) * SCH);
        float S1 = 0.f, S2 = 0.f;
#pragma unroll
        for (int s = 0; s < SCH / 4; s++) {
            float4 a = m1[s]; S1 += (a.x + a.y) + (a.z + a.w);
            float4 b = m2[s]; S2 += (b.x + b.y) + (b.z + b.w);
        }
        float nsafe = fmaxf(n, 1.0f);
        float miu = S1 / nsafe;
        float var = fmaxf(S2 / nsafe - miu * miu, 0.0f) + 1e-10f;
        float invs = rsqrtf(var);
        sinv[tid] = invs;
        snmu[tid] = -miu * invs;
    }

    const int clen = g_len[cls] >> 6;          // multiple of 16, <=256
    if (active) {
        // stage this chunk's entries (coalesced)
        const unsigned* __restrict__ pe = g_pairs + cls * FPX + sb * clen;
        for (int i = tid; i < clen; i += 128) {
            unsigned p = __ldg(pe + i);
            sidx[i] = (int)(p & 0xFFFFu) * 32;
            swt[i]  = (float)(p >> 16);
        }
    }
    __syncthreads();

    if (active) {
        const float2* __restrict__ ft2 = reinterpret_cast<const float2*>(g_ft);
        const float invsA = sinv[2 * lane],     nmuA = snmu[2 * lane];
        const float invsB = sinv[2 * lane + 1], nmuB = snmu[2 * lane + 1];
        float accPa[4] = {0.f, 0.f, 0.f, 0.f}, accNa[4] = {0.f, 0.f, 0.f, 0.f};
        float accPb[4] = {0.f, 0.f, 0.f, 0.f}, accNb[4] = {0.f, 0.f, 0.f, 0.f};

        const int qlen = clen >> 2;            // per-warp, multiple of 4
        const int base = wid * qlen;
        for (int i = 0; i < qlen; i += 4) {
            const int j = base + i;
            float2 f0 = ft2[sidx[j + 0] + lane];
            float2 f1 = ft2[sidx[j + 1] + lane];
            float2 f2 = ft2[sidx[j + 2] + lane];
            float2 f3 = ft2[sidx[j + 3] + lane];
            float w0 = swt[j + 0], w1 = swt[j + 1], w2 = swt[j + 2], w3 = swt[j + 3];
            px_work(f0.x, w0, invsA, nmuA, accPa, accNa);
            px_work(f0.y, w0, invsB, nmuB, accPb, accNb);
            px_work(f1.x, w1, invsA, nmuA, accPa, accNa);
            px_work(f1.y, w1, invsB, nmuB, accPb, accNb);
            px_work(f2.x, w2, invsA, nmuA, accPa, accNa);
            px_work(f2.y, w2, invsB, nmuB, accPb, accNb);
            px_work(f3.x, w3, invsA, nmuA, accPa, accNa);
            px_work(f3.y, w3, invsB, nmuB, accPb, accNb);
        }
#pragma unroll
        for (int k = 0; k < 4; k++) {
            stgP[wid][lane][k] = make_float2(accPa[k], accPb[k]);
            stgN[wid][lane][k] = make_float2(accNa[k], accNb[k]);
        }
    }
    __syncthreads();

    if (active && tid < DCH) {
        const int pi = tid >> 1, comp = tid & 1;
        float P[4], N[4];
#pragma unroll
        for (int k = 0; k < 4; k++) {
            float vP = 0.f, vN = 0.f;
#pragma unroll
            for (int w = 0; w < 4; w++) {
                float2 p2 = stgP[w][pi][k], n2 = stgN[w][pi][k];
                vP += comp ? p2.y : p2.x;
                vN += comp ? n2.y : n2.x;
            }
            P[k] = vP; N[k] = vN;
        }
        // P bank s -> bin 6-s ; N bank s -> bin s (far banks truncated)
        float4* bp = reinterpret_cast<float4*>(g_binp + ((cls * DCH + tid) * SCH + sb) * 8);
        bp[0] = make_float4(N[0], N[1], N[2], P[3] + N[3]);
        bp[1] = make_float4(P[2], P[1], P[0], 0.f);
    }
    __threadfence();
    if (tid == 0) {
        int t = atomicAdd(&g_ctick[cls], 1);
        sflag = (t == SCH - 1) ? 1 : 0;
    }
    __syncthreads();

    if (sflag) {
        __threadfence();
        float myloss = 0.f;
        if (active && tid < DCH) {
            float sbin[7] = {0.f, 0.f, 0.f, 0.f, 0.f, 0.f, 0.f};
            const float4* bp = reinterpret_cast<const float4*>(g_binp + (cls * DCH + tid) * SCH * 8);
            for (int s = 0; s < SCH; s++) {
                float4 v0 = bp[2 * s], v1 = bp[2 * s + 1];
                sbin[0] += v0.x; sbin[1] += v0.y; sbin[2] += v0.z; sbin[3] += v0.w;
                sbin[4] += v1.x; sbin[5] += v1.y; sbin[6] += v1.z;
            }
            float tot = 0.f;
#pragma unroll
            for (int ib = 0; ib < 7; ib++) tot += sbin[ib];
            float inv = 1.0f / fmaxf(tot, 1e-30f);
            const float targ[7] = {0.00443305f, 0.05400558f, 0.24203623f, 0.39905027f,
                                   0.24203623f, 0.05400558f, 0.00443305f};
            float L = 0.f;
#pragma unroll
            for (int ib = 0; ib < 7; ib++) {
                float dif = fabsf(sbin[ib] * inv - targ[ib]);
                L += (dif < 1.0f) ? 0.5f * dif * dif : (dif - 0.5f);
            }
            myloss = L;
        }
        float v = myloss;
#pragma unroll
        for (int o = 16; o; o >>= 1) v += __shfl_xor_sync(0xffffffffu, v, o);
        if (lane == 0) red[wid] = v;
        __syncthreads();
        if (tid == 0) {
            float sum = red[0] + red[1] + red[2] + red[3];
            g_closs[cls] = active ? sum * (1.0f / (7.0f * (float)DCH)) : 0.f;
            g_ctick[cls] = 0;   // reset for next graph replay
            __threadfence();
            int gt = atomicAdd(&g_gtick, 1);
            gflag = (gt == NCLS - 1) ? 1 : 0;
        }
        __syncthreads();
        if (gflag && tid == 0) {
            __threadfence();
            float num = 0.f, den = 0.f;
#pragma unroll
            for (int c = 0; c < NCLS; c++) {
                num += g_closs[c];
                den += (g_n[c] >= 1000.0f) ? 1.0f : 0.0f;
            }
            outp[0] = num / den;
            g_gtick = 0;        // reset for next graph replay
        }
    }
}

extern "C" void kernel_launch(void* const* d_in, const int* in_sizes, int n_in,
                              void* d_out, int out_size) {
    const float* feature;
    const int*   label;
    if (in_sizes[0] == DCH * FPX) {
        feature = (const float*)d_in[0];
        label   = (const int*)d_in[1];
    } else {
        feature = (const float*)d_in[1];
        label   = (const int*)d_in[0];
    }
    prep_kernel<<<320, 256>>>(feature, label);
    compact_kernel<<<NCLS, NTP>>>();
    mom_kernel<<<dim3(NCLS, SCH), 256>>>();
    kde_kernel<<<dim3(NCLS, SCH), 128>>>((float*)d_out);
}